// round 12
// baseline (speedup 1.0000x reference)
#include <cuda_runtime.h>
#include <math.h>

#define N_PTS 300000
#define KOFF 9
#define POOL_BLOCKS 1000  // 300 rows per block, exact
#define AHID 16           // attention hidden dim = COUT//4

typedef unsigned long long ull;

// ---------------- scratch (static device globals: allocation-free) ----------
__device__ float g_h[(size_t)N_PTS * 32];          // bottleneck activations
__device__ float g_ms[(size_t)N_PTS * 192];        // concat feat1|feat2|feat3
__device__ float g_pool_part[POOL_BLOCKS * 192];   // per-block partial maxima
__device__ float g_attn[192];                      // attention weights
__device__ float g_bn_s[5 * 64];                   // staged bn scales (pair-major)
__device__ float g_bn_b[5 * 64];                   // staged bn biases
// BN-scale-folded weights
__device__ float g_W1s[KOFF * 64 * 64];
__device__ float g_W3s[KOFF * 64 * 64];
__device__ float g_W2bs[KOFF * 32 * 64];
__device__ float g_W2as[64 * 32];
__device__ float g_Wfs[192 * 64];                  // attn * bnf_s folded

// ---------------- f32x2 helpers ---------------------------------------------
__device__ __forceinline__ ull pack2(float x, float y) {
    ull r; unsigned a = __float_as_uint(x), b = __float_as_uint(y);
    asm("mov.b64 %0, {%1, %2};" : "=l"(r) : "r"(a), "r"(b));
    return r;
}
__device__ __forceinline__ ull dup2(float x) {
    ull r; unsigned a = __float_as_uint(x);
    asm("mov.b64 %0, {%1, %1};" : "=l"(r) : "r"(a));
    return r;
}
#define FMA2(acc, f, w) asm("fma.rn.f32x2 %0, %1, %2, %0;" : "+l"(acc) : "l"(f), "l"(w))

// ---------------- bn select --------------------------------------------------
__global__ void bn_select_kernel(
    const float* a0, const float* b0, const float* a1, const float* b1,
    const float* a2, const float* b2, const float* a3, const float* b3,
    const float* a4, const float* b4)
{
    __shared__ float red[64];
    const float* pa[5] = {a0, a1, a2, a3, a4};
    const float* pb[5] = {b0, b1, b2, b3, b4};
    const int    ln[5] = {64, 64, 64, 64, 32};
    const int t = threadIdx.x;   // 64 threads
    for (int p = 0; p < 5; p++) {
        const int L = ln[p];
        red[t] = (t < L) ? pa[p][t] : 1e30f;
        __syncthreads();
        for (int s = 32; s > 0; s >>= 1) {
            if (t < s) red[t] = fminf(red[t], red[t + s]);
            __syncthreads();
        }
        const bool a_is_scale = (red[0] > 0.3f);
        __syncthreads();
        const float* ps = a_is_scale ? pa[p] : pb[p];
        const float* pv = a_is_scale ? pb[p] : pa[p];
        if (t < L) { g_bn_s[p * 64 + t] = ps[t]; g_bn_b[p * 64 + t] = pv[t]; }
        __syncthreads();
    }
}

// ---------------- fold bn scales into conv weights --------------------------
__global__ __launch_bounds__(256) void prep_weights_kernel(
    const float* __restrict__ W1, const float* __restrict__ W2a,
    const float* __restrict__ W2b, const float* __restrict__ W3) {
    const int i = blockIdx.x * 256 + threadIdx.x;
    if (i < KOFF * 64 * 64) {
        g_W1s[i] = W1[i] * g_bn_s[0 * 64 + (i & 63)];
        g_W3s[i] = W3[i] * g_bn_s[2 * 64 + (i & 63)];
    }
    if (i < KOFF * 32 * 64) g_W2bs[i] = W2b[i] * g_bn_s[1 * 64 + (i & 63)];
    if (i < 64 * 32)        g_W2as[i] = W2a[i] * g_bn_s[4 * 64 + (i & 31)];
}

// ---------------- bottleneck: h = relu(f @ W2a' + b2a) ----------------------
__global__ __launch_bounds__(256, 2) void h_kernel(const float* __restrict__ f) {
    __shared__ float Wsm[64 * 32];
    const int tid = threadIdx.x;
    for (int i = tid; i < 64 * 32 / 4; i += 256)
        ((float4*)Wsm)[i] = ((const float4*)g_W2as)[i];
    __syncthreads();

    const int n = blockIdx.x * 256 + tid;
    if (n >= N_PTS) return;
    ull acc[16];
#pragma unroll
    for (int p = 0; p < 16; p++) acc[p] = pack2(g_bn_b[4*64 + 2*p], g_bn_b[4*64 + 2*p + 1]);

    const float4* fr = (const float4*)(f + (size_t)n * 64);
    const ulonglong2* Wp = (const ulonglong2*)Wsm;
#pragma unroll 4
    for (int ch4 = 0; ch4 < 16; ch4++) {
        float4 fv = __ldg(fr + ch4);
#pragma unroll
        for (int cc = 0; cc < 4; cc++) {
            const float fs = cc == 0 ? fv.x : cc == 1 ? fv.y : cc == 2 ? fv.z : fv.w;
            const ull f2 = dup2(fs);
            const ulonglong2* w = Wp + (ch4 * 4 + cc) * 8;
#pragma unroll
            for (int q = 0; q < 8; q++) {
                ulonglong2 wv = w[q];
                FMA2(acc[2*q+0], f2, wv.x);
                FMA2(acc[2*q+1], f2, wv.y);
            }
        }
    }
#pragma unroll
    for (int q = 0; q < 8; q++) {
        unsigned l0, h0, l1, h1;
        asm("mov.b64 {%0, %1}, %2;" : "=r"(l0), "=r"(h0) : "l"(acc[2*q]));
        asm("mov.b64 {%0, %1}, %2;" : "=r"(l1), "=r"(h1) : "l"(acc[2*q+1]));
        float4 o;
        o.x = fmaxf(__uint_as_float(l0), 0.0f);
        o.y = fmaxf(__uint_as_float(h0), 0.0f);
        o.z = fmaxf(__uint_as_float(l1), 0.0f);
        o.w = fmaxf(__uint_as_float(h1), 0.0f);
        ((float4*)(g_h + (size_t)n * 32))[q] = o;
    }
}

// ---------------- unified conv kernel ----------------------------------------
// out[n, coff + 0..63] = relu( sum_k gather_k(fin) @ Wg[k] + bias[pidx] )
// fsel: 0 = external fin pointer, 1 = g_h, 2 = g_ms.
// Warp = 32 points: chgrp g = lid&7 (8 out-ch), octet o = lid>>3 (8 points).
// Gather buffer: pitch 32 floats, rotate-swizzled chunks:
//   chunk c of row r at  r*32 + ((c + 2*(r>>3)) & 7)*4
// -> consume LDS: 4 octets hit 4 disjoint bank-quads (1 wavefront, was 4-way
//    conflicted); stores stay at the 4-wavefront floor.
// Weight slabs per chgrp (+4 skew): weight LDS = full 128B wavefront.
template <int CI, int NK>
__global__ __launch_bounds__(512, 1) void conv_kernel(
    const float* __restrict__ fin_p, const int* __restrict__ nbr,
    int fsel, int wsel, int pidx, int coff, int ostride, float* __restrict__ out_p)
{
    extern __shared__ float sm[];
    const int SLAB = NK * CI * 8;
    const int WSTR = SLAB + 4;
    const float* fin = (fsel == 0) ? fin_p : (fsel == 1) ? (const float*)g_h
                      : (const float*)g_ms;
    float* outp = out_p ? out_p : (float*)g_ms;
    const float* Wg = (wsel == 0) ? g_W1s : (wsel == 1) ? g_W2bs
                     : (wsel == 2) ? g_W3s : g_Wfs;

    const int tid = threadIdx.x;
    for (int i = tid; i < 8 * SLAB; i += 512) {
        const int g = i / SLAB;
        const int j = i - g * SLAB;
        const int r = j >> 3;
        const int col = j & 7;
        sm[g * WSTR + j] = Wg[r * 64 + g * 8 + col];
    }
    __syncthreads();

    const int lid = tid & 31;
    const int wp0 = blockIdx.x * 512 + (tid >> 5) * 32;
    if (wp0 >= N_PTS) return;    // whole warps exit (N_PTS % 32 == 0)

    float* buf = sm + 8 * WSTR + (tid >> 5) * (32 * 32);

    const int g = lid & 7;
    const int o = lid >> 3;
    const int c0 = g * 8;

    ull acc[8][4];
#pragma unroll
    for (int p = 0; p < 8; p++)
#pragma unroll
        for (int j = 0; j < 4; j++)
            acc[p][j] = pack2(g_bn_b[pidx*64 + c0 + 2*j], g_bn_b[pidx*64 + c0 + 2*j + 1]);

    const ulonglong2* Wbase = (const ulonglong2*)(sm + g * WSTR);

#pragma unroll 1
    for (int k = 0; k < NK; k++) {
        if (nbr) {
            const int nbself = nbr[(size_t)k * N_PTS + wp0 + lid];
            if (__ballot_sync(0xffffffffu, nbself >= 0) == 0u) continue;
        }
#pragma unroll 1
        for (int seg = 0; seg < CI / 32; seg++) {
            __syncwarp();
#pragma unroll
            for (int i = 0; i < 8; i++) {
                const int r = o + 4 * i;
                const int nb = nbr ? nbr[(size_t)k * N_PTS + wp0 + r] : (wp0 + r);
                float4 v = make_float4(0.f, 0.f, 0.f, 0.f);
                if (nb >= 0)
                    v = __ldg((const float4*)(fin + (size_t)nb * CI + seg * 32) + g);
                *(float4*)(buf + r * 32 + (((g + 2 * (r >> 3)) & 7) << 2)) = v;
            }
            __syncwarp();
#pragma unroll
            for (int ch4 = 0; ch4 < 8; ch4++) {
                const int cbase = k * CI + seg * 32 + ch4 * 4;
                ulonglong2 w[4][2];
#pragma unroll
                for (int cc = 0; cc < 4; cc++) {
                    w[cc][0] = Wbase[(cbase + cc) * 2 + 0];
                    w[cc][1] = Wbase[(cbase + cc) * 2 + 1];
                }
                const int swc = ((ch4 + 2 * o) & 7) << 2;   // swizzled chunk offset
#pragma unroll
                for (int ph = 0; ph < 2; ph++) {
                    float4 fv[4];
#pragma unroll
                    for (int pp = 0; pp < 4; pp++)
                        fv[pp] = *(const float4*)(buf + (o * 8 + ph * 4 + pp) * 32 + swc);
#pragma unroll
                    for (int cc = 0; cc < 4; cc++) {
#pragma unroll
                        for (int pp = 0; pp < 4; pp++) {
                            const float fs = cc == 0 ? fv[pp].x : cc == 1 ? fv[pp].y
                                           : cc == 2 ? fv[pp].z : fv[pp].w;
                            const ull f2 = dup2(fs);
                            FMA2(acc[ph*4+pp][0], f2, w[cc][0].x);
                            FMA2(acc[ph*4+pp][1], f2, w[cc][0].y);
                            FMA2(acc[ph*4+pp][2], f2, w[cc][1].x);
                            FMA2(acc[ph*4+pp][3], f2, w[cc][1].y);
                        }
                    }
                }
            }
        }
    }

    const int myp0 = wp0 + o * 8;
#pragma unroll
    for (int p = 0; p < 8; p++) {
        float* orow = outp + (size_t)(myp0 + p) * ostride + coff + c0;
#pragma unroll
        for (int q = 0; q < 2; q++) {
            unsigned l0, h0, l1, h1;
            asm("mov.b64 {%0, %1}, %2;" : "=r"(l0), "=r"(h0) : "l"(acc[p][2*q]));
            asm("mov.b64 {%0, %1}, %2;" : "=r"(l1), "=r"(h1) : "l"(acc[p][2*q+1]));
            float4 ov;
            ov.x = fmaxf(__uint_as_float(l0), 0.0f);
            ov.y = fmaxf(__uint_as_float(h0), 0.0f);
            ov.z = fmaxf(__uint_as_float(l1), 0.0f);
            ov.w = fmaxf(__uint_as_float(h1), 0.0f);
            ((float4*)orow)[q] = ov;
        }
    }
}

// ---------------- max pool partials ------------------------------------------
__global__ __launch_bounds__(192) void pool_kernel() {
    const int t = threadIdx.x;
    const int rpb = N_PTS / POOL_BLOCKS;          // 300 exact
    const int r0 = blockIdx.x * rpb;
    const int r1 = r0 + rpb;
    float m = 0.0f;   // ms >= 0 (post-relu)
    for (int r = r0; r < r1; r++)
        m = fmaxf(m, g_ms[(size_t)r * 192 + t]);
    g_pool_part[blockIdx.x * 192 + t] = m;
}

// ---------------- SE attention + fold attn*bnf_s into Wf ---------------------
__global__ void attn_kernel(const float* __restrict__ A1w, const float* __restrict__ A1b,
                            const float* __restrict__ A2w, const float* __restrict__ A2b,
                            const float* __restrict__ Wf) {
    __shared__ float pool[192];
    __shared__ float r[AHID];
    const int t = threadIdx.x;
    float m = 0.0f;
    for (int b = 0; b < POOL_BLOCKS; b++)
        m = fmaxf(m, g_pool_part[b * 192 + t]);
    pool[t] = m;
    __syncthreads();
    if (t < AHID) {
        float a = A1b[t];
        for (int c = 0; c < 192; c++) a += pool[c] * A1w[c * AHID + t];
        r[t] = fmaxf(a, 0.0f);
    }
    __syncthreads();
    float z = A2b[t];
#pragma unroll
    for (int j = 0; j < AHID; j++) z += r[j] * A2w[j * 192 + t];
    const float a = 1.0f / (1.0f + expf(-z));
    g_attn[t] = a;
    for (int j = 0; j < 64; j++)
        g_Wfs[t * 64 + j] = Wf[t * 64 + j] * a * g_bn_s[3 * 64 + j];
}

// ---------------- launch ----------------------------------------------------
extern "C" void kernel_launch(void* const* d_in, const int* in_sizes, int n_in,
                              void* d_out, int out_size) {
    int i_feat = 0, i_W1 = 1, i_W2a = 4, i_W2b = 7, i_W3 = 10;
    int i_A1w = 13, i_A1b = 14, i_A2w = 15, i_A2b = 16, i_Wf = 17;
    int i_n1 = 20, i_n2 = 21;
    int p64[8] = {2, 3, 8, 9, 11, 12, 18, 19};
    int p32[2] = {5, 6};
    int c64 = 0, c32 = 0, c36864 = 0, c3072 = 0, c27 = 0;
    int t64[8], t32[2];
    for (int i = 0; i < n_in; i++) {
        const int s = in_sizes[i];
        switch (s) {
            case 19200000: i_feat = i; break;
            case 36864:    if (c36864 == 0) i_W1 = i; else i_W3 = i; c36864++; break;
            case 18432:    i_W2b = i; break;
            case 2048:     i_W2a = i; break;
            case 12288:    i_Wf = i; break;
            case 3072:     if (c3072 == 0) i_A1w = i; else i_A2w = i; c3072++; break;
            case 16:       i_A1b = i; break;
            case 192:      i_A2b = i; break;
            case 2700000:  if (c27 == 0) i_n1 = i; else i_n2 = i; c27++; break;
            case 64:       if (c64 < 8) t64[c64] = i; c64++; break;
            case 32:       if (c32 < 2) t32[c32] = i; c32++; break;
            default: break;
        }
    }
    if (c64 == 8) for (int j = 0; j < 8; j++) p64[j] = t64[j];
    if (c32 == 2) { p32[0] = t32[0]; p32[1] = t32[1]; }

    const float* features = (const float*)d_in[i_feat];
    const float* W1  = (const float*)d_in[i_W1];
    const float* W2a = (const float*)d_in[i_W2a];
    const float* W2b = (const float*)d_in[i_W2b];
    const float* W3  = (const float*)d_in[i_W3];
    const float* A1w = (const float*)d_in[i_A1w];
    const float* A1b = (const float*)d_in[i_A1b];
    const float* A2w = (const float*)d_in[i_A2w];
    const float* A2b = (const float*)d_in[i_A2b];
    const float* Wf  = (const float*)d_in[i_Wf];
    const int* nbr1  = (const int*)d_in[i_n1];
    const int* nbr2  = (const int*)d_in[i_n2];
    float* out = (float*)d_out;

    const int BUFS = 16 * 32 * 32 * 4;                       // 65536
    const int sm64 = 8 * (KOFF * 64 * 8 + 4) * 4 + BUFS;     // 213120
    const int sm32 = 8 * (KOFF * 32 * 8 + 4) * 4 + BUFS;     // 139392
    const int smf  = 8 * (192 * 8 + 4) * 4 + BUFS;           // 114816
    cudaFuncSetAttribute(conv_kernel<64, KOFF>, cudaFuncAttributeMaxDynamicSharedMemorySize, sm64);
    cudaFuncSetAttribute(conv_kernel<32, KOFF>, cudaFuncAttributeMaxDynamicSharedMemorySize, sm32);
    cudaFuncSetAttribute(conv_kernel<192, 1>,   cudaFuncAttributeMaxDynamicSharedMemorySize, smf);

    bn_select_kernel<<<1, 64>>>(
        (const float*)d_in[p64[0]], (const float*)d_in[p64[1]],   // bn1
        (const float*)d_in[p64[2]], (const float*)d_in[p64[3]],   // bn2b
        (const float*)d_in[p64[4]], (const float*)d_in[p64[5]],   // bn3
        (const float*)d_in[p64[6]], (const float*)d_in[p64[7]],   // bnf
        (const float*)d_in[p32[0]], (const float*)d_in[p32[1]]);  // bn2a
    prep_weights_kernel<<<(KOFF * 64 * 64 + 255) / 256, 256>>>(W1, W2a, W2b, W3);

    const int gp = (N_PTS + 511) / 512;   // 586
    const int gh = (N_PTS + 255) / 256;   // 1172
    h_kernel<<<gh, 256>>>(features);
    conv_kernel<64, KOFF><<<gp, 512, sm64>>>(features, nbr1, 0, /*wsel=*/0, /*pidx=*/0, /*coff=*/0,   192, nullptr);
    conv_kernel<32, KOFF><<<gp, 512, sm32>>>(nullptr,  nbr1, 1, /*wsel=*/1, /*pidx=*/1, /*coff=*/64,  192, nullptr);
    conv_kernel<64, KOFF><<<gp, 512, sm64>>>(features, nbr2, 0, /*wsel=*/2, /*pidx=*/2, /*coff=*/128, 192, nullptr);
    pool_kernel<<<POOL_BLOCKS, 192>>>();
    attn_kernel<<<1, 192>>>(A1w, A1b, A2w, A2b, Wf);
    conv_kernel<192, 1><<<gp, 512, smf>>>(nullptr, nullptr, 2, /*wsel=*/3, /*pidx=*/3, /*coff=*/0, 64, out);
}